// round 1
// baseline (speedup 1.0000x reference)
#include <cuda_runtime.h>
#include <cstdint>
#include <math.h>

// EBMAttention: B=8, S=2048, E=1024, H=1, TEMPERATURE=1
//   q = query@Wq^T+bq ; k = key@Wk^T+bk ; v = value@Wv^T+bv
//   kt = k @ energy_W
//   energy = q @ kt^T   (masked: mask==0 -> -1e9)
//   attn = softmax(-energy)
//   out = attn @ v
// Outputs concatenated: out [B,S,E] then attn [B,1,S,S].

#define E_DIM 1024
#define S_DIM 2048
#define B_DIM 8
#define MS (B_DIM * S_DIM)   // 16384

// Scratch (device globals: no allocations allowed)
__device__ float g_Q [MS * E_DIM];
__device__ float g_K [MS * E_DIM];
__device__ float g_V [MS * E_DIM];
__device__ float g_KT[MS * E_DIM];

#define BM 128
#define BN 128
#define BK 16

typedef unsigned long long u64;

// packed f32x2 FMA: c.lo += a.lo*b.lo ; c.hi += a.hi*b.hi
__device__ __forceinline__ void fma2(u64& c, u64 a, u64 b) {
    asm("fma.rn.f32x2 %0, %1, %2, %0;" : "+l"(c) : "l"(a), "l"(b));
}

// ---------------------------------------------------------------------------
// NT GEMM: C[M,N] = A[M,K] * B[N,K]^T (+ bias).  A,B k-contiguous rows.
// Batched via blockIdx.z with element strides sA/sB/sC.
// ---------------------------------------------------------------------------
template<bool HAS_BIAS>
__global__ __launch_bounds__(256, 2)
void sgemm_nt(const float* __restrict__ A, const float* __restrict__ B,
              const float* __restrict__ bias, float* __restrict__ C,
              int M, int N, int K,
              long long sA, long long sB, long long sC)
{
    __shared__ float As2[BK][2 * BM];   // A values duplicated: [k][2m]={a,a}
    __shared__ float Bs [BK][BN];

    const int t  = threadIdx.x;
    const int m0 = blockIdx.y * BM;
    const int n0 = blockIdx.x * BN;
    A += (size_t)blockIdx.z * sA;
    B += (size_t)blockIdx.z * sB;
    C += (size_t)blockIdx.z * sC;

    const int lr = t >> 1;          // 0..127 : tile row for loads
    const int lk = (t & 1) * 4;     // 0 or 4 : k sub-offset

    const int ty8 = (t >> 4) * 8;   // 0..120 : compute row base
    const int tx8 = (t & 15) * 8;   // 0..120 : compute col base

    u64 c2[8][4];
    #pragma unroll
    for (int i = 0; i < 8; i++)
        #pragma unroll
        for (int j = 0; j < 4; j++) c2[i][j] = 0ull;

    for (int k0 = 0; k0 < K; k0 += BK) {
        const float4 a0 = *(const float4*)(A + (size_t)(m0 + lr) * K + k0 + lk);
        const float4 a1 = *(const float4*)(A + (size_t)(m0 + lr) * K + k0 + lk + 8);
        const float4 b0 = *(const float4*)(B + (size_t)(n0 + lr) * K + k0 + lk);
        const float4 b1 = *(const float4*)(B + (size_t)(n0 + lr) * K + k0 + lk + 8);

        __syncthreads();   // previous tile fully consumed

        *(float2*)&As2[lk + 0][2 * lr] = make_float2(a0.x, a0.x);
        *(float2*)&As2[lk + 1][2 * lr] = make_float2(a0.y, a0.y);
        *(float2*)&As2[lk + 2][2 * lr] = make_float2(a0.z, a0.z);
        *(float2*)&As2[lk + 3][2 * lr] = make_float2(a0.w, a0.w);
        *(float2*)&As2[lk + 8][2 * lr] = make_float2(a1.x, a1.x);
        *(float2*)&As2[lk + 9][2 * lr] = make_float2(a1.y, a1.y);
        *(float2*)&As2[lk +10][2 * lr] = make_float2(a1.z, a1.z);
        *(float2*)&As2[lk +11][2 * lr] = make_float2(a1.w, a1.w);
        Bs[lk + 0][lr] = b0.x;  Bs[lk + 1][lr] = b0.y;
        Bs[lk + 2][lr] = b0.z;  Bs[lk + 3][lr] = b0.w;
        Bs[lk + 8][lr] = b1.x;  Bs[lk + 9][lr] = b1.y;
        Bs[lk +10][lr] = b1.z;  Bs[lk +11][lr] = b1.w;

        __syncthreads();

        #pragma unroll
        for (int kk = 0; kk < BK; kk++) {
            u64 a2[8], b2[4];
            #pragma unroll
            for (int i = 0; i < 8; i++)
                a2[i] = *(const u64*)&As2[kk][2 * (ty8 + i)];
            #pragma unroll
            for (int j = 0; j < 4; j++)
                b2[j] = *(const u64*)&Bs[kk][tx8 + 2 * j];
            #pragma unroll
            for (int i = 0; i < 8; i++)
                #pragma unroll
                for (int j = 0; j < 4; j++)
                    fma2(c2[i][j], a2[i], b2[j]);
        }
    }

    float bv[8];
    #pragma unroll
    for (int jj = 0; jj < 8; jj++)
        bv[jj] = HAS_BIAS ? bias[n0 + tx8 + jj] : 0.0f;

    #pragma unroll
    for (int i = 0; i < 8; i++) {
        float o[8];
        #pragma unroll
        for (int j = 0; j < 4; j++) {
            float2 v = *(float2*)&c2[i][j];
            o[2 * j + 0] = v.x + bv[2 * j + 0];
            o[2 * j + 1] = v.y + bv[2 * j + 1];
        }
        float* Cp = C + (size_t)(m0 + ty8 + i) * N + n0 + tx8;
        *(float4*)(Cp)     = make_float4(o[0], o[1], o[2], o[3]);
        *(float4*)(Cp + 4) = make_float4(o[4], o[5], o[6], o[7]);
    }
}

// ---------------------------------------------------------------------------
// NN GEMM: C[M,N] = A[M,K] * B[K,N].  B n-contiguous rows (ldb = N).
// ---------------------------------------------------------------------------
__global__ __launch_bounds__(256, 2)
void sgemm_nn(const float* __restrict__ A, const float* __restrict__ B,
              float* __restrict__ C,
              int M, int N, int K,
              long long sA, long long sB, long long sC)
{
    __shared__ float As2[BK][2 * BM];
    __shared__ float Bs [BK][BN];

    const int t  = threadIdx.x;
    const int m0 = blockIdx.y * BM;
    const int n0 = blockIdx.x * BN;
    A += (size_t)blockIdx.z * sA;
    B += (size_t)blockIdx.z * sB;
    C += (size_t)blockIdx.z * sC;

    const int lr  = t >> 1;         // A loader row
    const int lk  = (t & 1) * 4;    // A loader k sub-offset
    const int bkr = t >> 5;         // 0..7 : B loader k row
    const int bn4 = (t & 31) * 4;   // B loader col

    const int ty8 = (t >> 4) * 8;
    const int tx8 = (t & 15) * 8;

    u64 c2[8][4];
    #pragma unroll
    for (int i = 0; i < 8; i++)
        #pragma unroll
        for (int j = 0; j < 4; j++) c2[i][j] = 0ull;

    for (int k0 = 0; k0 < K; k0 += BK) {
        const float4 a0 = *(const float4*)(A + (size_t)(m0 + lr) * K + k0 + lk);
        const float4 a1 = *(const float4*)(A + (size_t)(m0 + lr) * K + k0 + lk + 8);
        const float4 b0 = *(const float4*)(B + (size_t)(k0 + bkr)     * N + n0 + bn4);
        const float4 b1 = *(const float4*)(B + (size_t)(k0 + bkr + 8) * N + n0 + bn4);

        __syncthreads();

        *(float2*)&As2[lk + 0][2 * lr] = make_float2(a0.x, a0.x);
        *(float2*)&As2[lk + 1][2 * lr] = make_float2(a0.y, a0.y);
        *(float2*)&As2[lk + 2][2 * lr] = make_float2(a0.z, a0.z);
        *(float2*)&As2[lk + 3][2 * lr] = make_float2(a0.w, a0.w);
        *(float2*)&As2[lk + 8][2 * lr] = make_float2(a1.x, a1.x);
        *(float2*)&As2[lk + 9][2 * lr] = make_float2(a1.y, a1.y);
        *(float2*)&As2[lk +10][2 * lr] = make_float2(a1.z, a1.z);
        *(float2*)&As2[lk +11][2 * lr] = make_float2(a1.w, a1.w);
        *(float4*)&Bs[bkr    ][bn4] = b0;
        *(float4*)&Bs[bkr + 8][bn4] = b1;

        __syncthreads();

        #pragma unroll
        for (int kk = 0; kk < BK; kk++) {
            u64 a2[8], b2[4];
            #pragma unroll
            for (int i = 0; i < 8; i++)
                a2[i] = *(const u64*)&As2[kk][2 * (ty8 + i)];
            #pragma unroll
            for (int j = 0; j < 4; j++)
                b2[j] = *(const u64*)&Bs[kk][tx8 + 2 * j];
            #pragma unroll
            for (int i = 0; i < 8; i++)
                #pragma unroll
                for (int j = 0; j < 4; j++)
                    fma2(c2[i][j], a2[i], b2[j]);
        }
    }

    #pragma unroll
    for (int i = 0; i < 8; i++) {
        float o[8];
        #pragma unroll
        for (int j = 0; j < 4; j++) {
            float2 v = *(float2*)&c2[i][j];
            o[2 * j + 0] = v.x;
            o[2 * j + 1] = v.y;
        }
        float* Cp = C + (size_t)(m0 + ty8 + i) * N + n0 + tx8;
        *(float4*)(Cp)     = make_float4(o[0], o[1], o[2], o[3]);
        *(float4*)(Cp + 4) = make_float4(o[4], o[5], o[6], o[7]);
    }
}

// ---------------------------------------------------------------------------
// Row softmax of -energy with mask, in place.  One block per (b,q) row.
//   x = (mask==0) ? 1e9 : -energy ;  attn = softmax(x)
// ---------------------------------------------------------------------------
__global__ void softmax_rows(float* __restrict__ attn, const int* __restrict__ mask)
{
    __shared__ float red[256];
    const int row = blockIdx.x;            // b*S + q
    const int q   = row & (S_DIM - 1);
    float* rp = attn + (size_t)row * S_DIM;
    const int* mp = mask + (size_t)q * S_DIM;
    const int t = threadIdx.x;

    float x[8];
    float mx = -3.402823e38f;
    #pragma unroll
    for (int r = 0; r < 8; r++) {
        const int j = t + r * 256;
        const float e = rp[j];
        const int  m  = mp[j];
        const float v = (m == 0) ? 1e9f : -e;
        x[r] = v;
        mx = fmaxf(mx, v);
    }
    red[t] = mx; __syncthreads();
    #pragma unroll
    for (int s = 128; s > 0; s >>= 1) {
        if (t < s) red[t] = fmaxf(red[t], red[t + s]);
        __syncthreads();
    }
    mx = red[0]; __syncthreads();

    float ex[8];
    float sum = 0.f;
    #pragma unroll
    for (int r = 0; r < 8; r++) {
        ex[r] = expf(x[r] - mx);
        sum += ex[r];
    }
    red[t] = sum; __syncthreads();
    #pragma unroll
    for (int s = 128; s > 0; s >>= 1) {
        if (t < s) red[t] += red[t + s];
        __syncthreads();
    }
    const float inv = 1.0f / red[0];
    #pragma unroll
    for (int r = 0; r < 8; r++)
        rp[t + r * 256] = ex[r] * inv;
}

// ---------------------------------------------------------------------------
extern "C" void kernel_launch(void* const* d_in, const int* in_sizes, int n_in,
                              void* d_out, int out_size)
{
    const float* query = (const float*)d_in[0];
    const float* key_  = (const float*)d_in[1];
    const float* value = (const float*)d_in[2];
    const int*   mask  = (const int*)  d_in[3];
    const float* Wq    = (const float*)d_in[4];
    const float* bq    = (const float*)d_in[5];
    const float* Wk    = (const float*)d_in[6];
    const float* bk    = (const float*)d_in[7];
    const float* Wv    = (const float*)d_in[8];
    const float* bv    = (const float*)d_in[9];
    const float* eW    = (const float*)d_in[10];

    float* outp = (float*)d_out;                                  // [B,S,E]
    float* attn = outp + (size_t)B_DIM * S_DIM * E_DIM;           // [B,S,S]

    float *Qb, *Kb, *Vb, *KTb;
    cudaGetSymbolAddress((void**)&Qb,  g_Q);
    cudaGetSymbolAddress((void**)&Kb,  g_K);
    cudaGetSymbolAddress((void**)&Vb,  g_V);
    cudaGetSymbolAddress((void**)&KTb, g_KT);

    const dim3 blk(256);

    // 1) projections: [16384,1024] = X @ W^T + b
    const dim3 gProj(E_DIM / BN, MS / BM, 1);
    sgemm_nt<true><<<gProj, blk>>>(query, Wq, bq, Qb, MS, E_DIM, E_DIM, 0, 0, 0);
    sgemm_nt<true><<<gProj, blk>>>(key_,  Wk, bk, Kb, MS, E_DIM, E_DIM, 0, 0, 0);
    sgemm_nt<true><<<gProj, blk>>>(value, Wv, bv, Vb, MS, E_DIM, E_DIM, 0, 0, 0);

    // 2) kt = k @ energy_W : [16384,1024]
    sgemm_nn<<<gProj, blk>>>(Kb, eW, KTb, MS, E_DIM, E_DIM, 0, 0, 0);

    // 3) energy[b] = Q_b @ KT_b^T : [2048,2048] x 8, written into attn region
    const dim3 gE(S_DIM / BN, S_DIM / BM, B_DIM);
    sgemm_nt<false><<<gE, blk>>>(Qb, KTb, nullptr, attn,
                                 S_DIM, S_DIM, E_DIM,
                                 (long long)S_DIM * E_DIM,
                                 (long long)S_DIM * E_DIM,
                                 (long long)S_DIM * S_DIM);

    // 4) attn = softmax(-energy) with mask, in place
    softmax_rows<<<MS, 256>>>(attn, mask);

    // 5) out[b] = attn_b @ V_b : [2048,1024] x 8
    const dim3 gO(E_DIM / BN, S_DIM / BM, B_DIM);
    sgemm_nn<<<gO, blk>>>(attn, Vb, outp,
                          S_DIM, E_DIM, S_DIM,
                          (long long)S_DIM * S_DIM,
                          (long long)S_DIM * E_DIM,
                          (long long)S_DIM * E_DIM);
}

// round 3
// speedup vs baseline: 1.0005x; 1.0005x over previous
#include <cuda_runtime.h>
#include <cstdint>
#include <math.h>

// EBMAttention: B=8, S=2048, E=1024, H=1, TEMPERATURE=1
//   q = query@Wq^T+bq ; k = key@Wk^T+bk ; v = value@Wv^T+bv
//   kt = k @ energy_W
//   energy = q @ kt^T   (masked: mask==0 -> -1e9)
//   attn = softmax(-energy)
//   out = attn @ v
// Outputs concatenated: out [B,S,E] then attn [B,1,S,S].

#define E_DIM 1024
#define S_DIM 2048
#define B_DIM 8
#define MS (B_DIM * S_DIM)   // 16384

// Scratch (device globals: no allocations allowed)
__device__ float g_Q [MS * E_DIM];
__device__ float g_K [MS * E_DIM];
__device__ float g_V [MS * E_DIM];
__device__ float g_KT[MS * E_DIM];

#define BM 128
#define BN 128
#define BK 16

typedef unsigned long long u64;

// packed f32x2 FMA: c.lo += a.lo*b.lo ; c.hi += a.hi*b.hi
__device__ __forceinline__ void fma2(u64& c, u64 a, u64 b) {
    asm("fma.rn.f32x2 %0, %1, %2, %0;" : "+l"(c) : "l"(a), "l"(b));
}

// ---------------------------------------------------------------------------
// NT GEMM: C[M,N] = A[M,K] * B[N,K]^T (+ bias).  A,B k-contiguous rows.
// Batched via blockIdx.z with element strides sA/sB/sC.
// ---------------------------------------------------------------------------
template<bool HAS_BIAS>
__global__ __launch_bounds__(256, 2)
void sgemm_nt(const float* __restrict__ A, const float* __restrict__ B,
              const float* __restrict__ bias, float* __restrict__ C,
              int M, int N, int K,
              long long sA, long long sB, long long sC)
{
    __shared__ float As2[BK][2 * BM];   // A values duplicated: [k][2m]={a,a}
    __shared__ float Bs [BK][BN];

    const int t  = threadIdx.x;
    const int m0 = blockIdx.y * BM;
    const int n0 = blockIdx.x * BN;
    A += (size_t)blockIdx.z * sA;
    B += (size_t)blockIdx.z * sB;
    C += (size_t)blockIdx.z * sC;

    const int lr = t >> 1;          // 0..127 : tile row for loads
    const int lk = (t & 1) * 4;     // 0 or 4 : k sub-offset

    const int ty8 = (t >> 4) * 8;   // 0..120 : compute row base
    const int tx8 = (t & 15) * 8;   // 0..120 : compute col base

    u64 c2[8][4];
    #pragma unroll
    for (int i = 0; i < 8; i++)
        #pragma unroll
        for (int j = 0; j < 4; j++) c2[i][j] = 0ull;

    for (int k0 = 0; k0 < K; k0 += BK) {
        const float4 a0 = *(const float4*)(A + (size_t)(m0 + lr) * K + k0 + lk);
        const float4 a1 = *(const float4*)(A + (size_t)(m0 + lr) * K + k0 + lk + 8);
        const float4 b0 = *(const float4*)(B + (size_t)(n0 + lr) * K + k0 + lk);
        const float4 b1 = *(const float4*)(B + (size_t)(n0 + lr) * K + k0 + lk + 8);

        __syncthreads();   // previous tile fully consumed

        *(float2*)&As2[lk + 0][2 * lr] = make_float2(a0.x, a0.x);
        *(float2*)&As2[lk + 1][2 * lr] = make_float2(a0.y, a0.y);
        *(float2*)&As2[lk + 2][2 * lr] = make_float2(a0.z, a0.z);
        *(float2*)&As2[lk + 3][2 * lr] = make_float2(a0.w, a0.w);
        *(float2*)&As2[lk + 8][2 * lr] = make_float2(a1.x, a1.x);
        *(float2*)&As2[lk + 9][2 * lr] = make_float2(a1.y, a1.y);
        *(float2*)&As2[lk +10][2 * lr] = make_float2(a1.z, a1.z);
        *(float2*)&As2[lk +11][2 * lr] = make_float2(a1.w, a1.w);
        Bs[lk + 0][lr] = b0.x;  Bs[lk + 1][lr] = b0.y;
        Bs[lk + 2][lr] = b0.z;  Bs[lk + 3][lr] = b0.w;
        Bs[lk + 8][lr] = b1.x;  Bs[lk + 9][lr] = b1.y;
        Bs[lk +10][lr] = b1.z;  Bs[lk +11][lr] = b1.w;

        __syncthreads();

        #pragma unroll
        for (int kk = 0; kk < BK; kk++) {
            u64 a2[8], b2[4];
            #pragma unroll
            for (int i = 0; i < 8; i++)
                a2[i] = *(const u64*)&As2[kk][2 * (ty8 + i)];
            #pragma unroll
            for (int j = 0; j < 4; j++)
                b2[j] = *(const u64*)&Bs[kk][tx8 + 2 * j];
            #pragma unroll
            for (int i = 0; i < 8; i++)
                #pragma unroll
                for (int j = 0; j < 4; j++)
                    fma2(c2[i][j], a2[i], b2[j]);
        }
    }

    float bv[8];
    #pragma unroll
    for (int jj = 0; jj < 8; jj++)
        bv[jj] = HAS_BIAS ? bias[n0 + tx8 + jj] : 0.0f;

    #pragma unroll
    for (int i = 0; i < 8; i++) {
        float o[8];
        #pragma unroll
        for (int j = 0; j < 4; j++) {
            float2 v = *(float2*)&c2[i][j];
            o[2 * j + 0] = v.x + bv[2 * j + 0];
            o[2 * j + 1] = v.y + bv[2 * j + 1];
        }
        float* Cp = C + (size_t)(m0 + ty8 + i) * N + n0 + tx8;
        *(float4*)(Cp)     = make_float4(o[0], o[1], o[2], o[3]);
        *(float4*)(Cp + 4) = make_float4(o[4], o[5], o[6], o[7]);
    }
}

// ---------------------------------------------------------------------------
// NN GEMM: C[M,N] = A[M,K] * B[K,N].  B n-contiguous rows (ldb = N).
// ---------------------------------------------------------------------------
__global__ __launch_bounds__(256, 2)
void sgemm_nn(const float* __restrict__ A, const float* __restrict__ B,
              float* __restrict__ C,
              int M, int N, int K,
              long long sA, long long sB, long long sC)
{
    __shared__ float As2[BK][2 * BM];
    __shared__ float Bs [BK][BN];

    const int t  = threadIdx.x;
    const int m0 = blockIdx.y * BM;
    const int n0 = blockIdx.x * BN;
    A += (size_t)blockIdx.z * sA;
    B += (size_t)blockIdx.z * sB;
    C += (size_t)blockIdx.z * sC;

    const int lr  = t >> 1;         // A loader row
    const int lk  = (t & 1) * 4;    // A loader k sub-offset
    const int bkr = t >> 5;         // 0..7 : B loader k row
    const int bn4 = (t & 31) * 4;   // B loader col

    const int ty8 = (t >> 4) * 8;
    const int tx8 = (t & 15) * 8;

    u64 c2[8][4];
    #pragma unroll
    for (int i = 0; i < 8; i++)
        #pragma unroll
        for (int j = 0; j < 4; j++) c2[i][j] = 0ull;

    for (int k0 = 0; k0 < K; k0 += BK) {
        const float4 a0 = *(const float4*)(A + (size_t)(m0 + lr) * K + k0 + lk);
        const float4 a1 = *(const float4*)(A + (size_t)(m0 + lr) * K + k0 + lk + 8);
        const float4 b0 = *(const float4*)(B + (size_t)(k0 + bkr)     * N + n0 + bn4);
        const float4 b1 = *(const float4*)(B + (size_t)(k0 + bkr + 8) * N + n0 + bn4);

        __syncthreads();

        *(float2*)&As2[lk + 0][2 * lr] = make_float2(a0.x, a0.x);
        *(float2*)&As2[lk + 1][2 * lr] = make_float2(a0.y, a0.y);
        *(float2*)&As2[lk + 2][2 * lr] = make_float2(a0.z, a0.z);
        *(float2*)&As2[lk + 3][2 * lr] = make_float2(a0.w, a0.w);
        *(float2*)&As2[lk + 8][2 * lr] = make_float2(a1.x, a1.x);
        *(float2*)&As2[lk + 9][2 * lr] = make_float2(a1.y, a1.y);
        *(float2*)&As2[lk +10][2 * lr] = make_float2(a1.z, a1.z);
        *(float2*)&As2[lk +11][2 * lr] = make_float2(a1.w, a1.w);
        *(float4*)&Bs[bkr    ][bn4] = b0;
        *(float4*)&Bs[bkr + 8][bn4] = b1;

        __syncthreads();

        #pragma unroll
        for (int kk = 0; kk < BK; kk++) {
            u64 a2[8], b2[4];
            #pragma unroll
            for (int i = 0; i < 8; i++)
                a2[i] = *(const u64*)&As2[kk][2 * (ty8 + i)];
            #pragma unroll
            for (int j = 0; j < 4; j++)
                b2[j] = *(const u64*)&Bs[kk][tx8 + 2 * j];
            #pragma unroll
            for (int i = 0; i < 8; i++)
                #pragma unroll
                for (int j = 0; j < 4; j++)
                    fma2(c2[i][j], a2[i], b2[j]);
        }
    }

    #pragma unroll
    for (int i = 0; i < 8; i++) {
        float o[8];
        #pragma unroll
        for (int j = 0; j < 4; j++) {
            float2 v = *(float2*)&c2[i][j];
            o[2 * j + 0] = v.x;
            o[2 * j + 1] = v.y;
        }
        float* Cp = C + (size_t)(m0 + ty8 + i) * N + n0 + tx8;
        *(float4*)(Cp)     = make_float4(o[0], o[1], o[2], o[3]);
        *(float4*)(Cp + 4) = make_float4(o[4], o[5], o[6], o[7]);
    }
}

// ---------------------------------------------------------------------------
// Row softmax of -energy with mask, in place.  One block per (b,q) row.
//   x = (mask==0) ? 1e9 : -energy ;  attn = softmax(x)
// ---------------------------------------------------------------------------
__global__ void softmax_rows(float* __restrict__ attn, const int* __restrict__ mask)
{
    __shared__ float red[256];
    const int row = blockIdx.x;            // b*S + q
    const int q   = row & (S_DIM - 1);
    float* rp = attn + (size_t)row * S_DIM;
    const int* mp = mask + (size_t)q * S_DIM;
    const int t = threadIdx.x;

    float x[8];
    float mx = -3.402823e38f;
    #pragma unroll
    for (int r = 0; r < 8; r++) {
        const int j = t + r * 256;
        const float e = rp[j];
        const int  m  = mp[j];
        const float v = (m == 0) ? 1e9f : -e;
        x[r] = v;
        mx = fmaxf(mx, v);
    }
    red[t] = mx; __syncthreads();
    #pragma unroll
    for (int s = 128; s > 0; s >>= 1) {
        if (t < s) red[t] = fmaxf(red[t], red[t + s]);
        __syncthreads();
    }
    mx = red[0]; __syncthreads();

    float ex[8];
    float sum = 0.f;
    #pragma unroll
    for (int r = 0; r < 8; r++) {
        ex[r] = expf(x[r] - mx);
        sum += ex[r];
    }
    red[t] = sum; __syncthreads();
    #pragma unroll
    for (int s = 128; s > 0; s >>= 1) {
        if (t < s) red[t] += red[t + s];
        __syncthreads();
    }
    const float inv = 1.0f / red[0];
    #pragma unroll
    for (int r = 0; r < 8; r++)
        rp[t + r * 256] = ex[r] * inv;
}

// ---------------------------------------------------------------------------
extern "C" void kernel_launch(void* const* d_in, const int* in_sizes, int n_in,
                              void* d_out, int out_size)
{
    const float* query = (const float*)d_in[0];
    const float* key_  = (const float*)d_in[1];
    const float* value = (const float*)d_in[2];
    const int*   mask  = (const int*)  d_in[3];
    const float* Wq    = (const float*)d_in[4];
    const float* bq    = (const float*)d_in[5];
    const float* Wk    = (const float*)d_in[6];
    const float* bk    = (const float*)d_in[7];
    const float* Wv    = (const float*)d_in[8];
    const float* bv    = (const float*)d_in[9];
    const float* eW    = (const float*)d_in[10];

    float* outp = (float*)d_out;                                  // [B,S,E]
    float* attn = outp + (size_t)B_DIM * S_DIM * E_DIM;           // [B,S,S]

    float *Qb, *Kb, *Vb, *KTb;
    cudaGetSymbolAddress((void**)&Qb,  g_Q);
    cudaGetSymbolAddress((void**)&Kb,  g_K);
    cudaGetSymbolAddress((void**)&Vb,  g_V);
    cudaGetSymbolAddress((void**)&KTb, g_KT);

    const dim3 blk(256);

    // 1) projections: [16384,1024] = X @ W^T + b
    const dim3 gProj(E_DIM / BN, MS / BM, 1);
    sgemm_nt<true><<<gProj, blk>>>(query, Wq, bq, Qb, MS, E_DIM, E_DIM, 0, 0, 0);
    sgemm_nt<true><<<gProj, blk>>>(key_,  Wk, bk, Kb, MS, E_DIM, E_DIM, 0, 0, 0);
    sgemm_nt<true><<<gProj, blk>>>(value, Wv, bv, Vb, MS, E_DIM, E_DIM, 0, 0, 0);

    // 2) kt = k @ energy_W : [16384,1024]
    sgemm_nn<<<gProj, blk>>>(Kb, eW, KTb, MS, E_DIM, E_DIM, 0, 0, 0);

    // 3) energy[b] = Q_b @ KT_b^T : [2048,2048] x 8, written into attn region
    const dim3 gE(S_DIM / BN, S_DIM / BM, B_DIM);
    sgemm_nt<false><<<gE, blk>>>(Qb, KTb, nullptr, attn,
                                 S_DIM, S_DIM, E_DIM,
                                 (long long)S_DIM * E_DIM,
                                 (long long)S_DIM * E_DIM,
                                 (long long)S_DIM * S_DIM);

    // 4) attn = softmax(-energy) with mask, in place
    softmax_rows<<<MS, 256>>>(attn, mask);

    // 5) out[b] = attn_b @ V_b : [2048,1024] x 8
    const dim3 gO(E_DIM / BN, S_DIM / BM, B_DIM);
    sgemm_nn<<<gO, blk>>>(attn, Vb, outp,
                          S_DIM, E_DIM, S_DIM,
                          (long long)S_DIM * S_DIM,
                          (long long)S_DIM * E_DIM,
                          (long long)S_DIM * E_DIM);
}

// round 5
// speedup vs baseline: 1.5011x; 1.5003x over previous
#include <cuda_runtime.h>
#include <cuda_bf16.h>
#include <cstdint>
#include <math.h>

// EBMAttention B=8,S=2048,E=1024 — all GEMMs via mma.sync bf16 (HMMA) with
// error-compensated limb splitting. PTX target is plain sm_100 (no tcgen05).
#define E_DIM 1024
#define S_DIM 2048
#define B_DIM 8
#define MS    16384

typedef unsigned int u32;
typedef unsigned long long u64;

#define NQ  16777216ull
#define WN  1048576ull
#define ATN 33554432ull
__device__ __align__(256) __nv_bfloat16 g_sb[19 * NQ + 2 * ATN + 11 * WN];

// ---------------- PTX helpers (all legal on sm_100 baseline) ----------------
__device__ __forceinline__ u32 s2u(const void* p) {
    return (u32)__cvta_generic_to_shared(p);
}
__device__ __forceinline__ void cp16(u32 sa, const void* gp) {
    asm volatile("cp.async.cg.shared.global [%0], [%1], 16;" :: "r"(sa), "l"(gp) : "memory");
}
#define CP_COMMIT() asm volatile("cp.async.commit_group;" ::: "memory")
#define CP_WAIT1()  asm volatile("cp.async.wait_group 1;" ::: "memory")
#define CP_WAIT0()  asm volatile("cp.async.wait_group 0;" ::: "memory")

__device__ __forceinline__ void ldsm4(u32* r, u32 addr) {
    asm volatile("ldmatrix.sync.aligned.m8n8.x4.shared.b16 {%0,%1,%2,%3}, [%4];"
                 : "=r"(r[0]), "=r"(r[1]), "=r"(r[2]), "=r"(r[3]) : "r"(addr));
}
__device__ __forceinline__ void mma16816(float* c, const u32* a, const u32* b) {
    asm volatile(
        "mma.sync.aligned.m16n8k16.row.col.f32.bf16.bf16.f32 "
        "{%0,%1,%2,%3}, {%4,%5,%6,%7}, {%8,%9}, {%0,%1,%2,%3};"
        : "+f"(c[0]), "+f"(c[1]), "+f"(c[2]), "+f"(c[3])
        : "r"(a[0]), "r"(a[1]), "r"(a[2]), "r"(a[3]), "r"(b[0]), "r"(b[1]));
}

__device__ __forceinline__ void split3(float x, __nv_bfloat16& h0, __nv_bfloat16& h1, __nv_bfloat16& h2) {
    h0 = __float2bfloat16(x);
    float r = x - __bfloat162float(h0);
    h1 = __float2bfloat16(r);
    h2 = __float2bfloat16(r - __bfloat162float(h1));
}
__device__ __forceinline__ void split2(float x, __nv_bfloat16& h0, __nv_bfloat16& h1) {
    h0 = __float2bfloat16(x);
    h1 = __float2bfloat16(x - __bfloat162float(h0));
}

struct GArgs {
    const __nv_bfloat16 *A0, *A1, *A2, *B0, *B1, *B2;
    const float* bias;
    float* Cf;
    __nv_bfloat16 *C0, *C1, *C2;
    int ldA, ldB, ldC, K;
    long long sA, sB, sC;
};

// Tile geometry: CTA 128x128, BK=32 (64B rows), smem rows padded to 80B
// (bank stride 20 -> 8-row ldmatrix fetch hits all 32 banks, conflict-free).
#define ROWB  80
#define TILEB (128 * ROWB)   // 10240 B per 128x32 bf16 tile

// One 128-row x 32-col bf16 tile -> smem via cp.async (2 x 16B per thread)
__device__ __forceinline__ void cp_tile(const __nv_bfloat16* __restrict__ src,
                                        int row0, int k0, int ld, u32 sbase)
{
    const int t   = threadIdx.x;
    const int row = t >> 1;
    const int cb  = (t & 1) * 32;
    const char* gp = (const char*)(src + (size_t)(row0 + row) * ld + k0) + cb;
    const u32 sa = sbase + (u32)(row * ROWB + cb);
    cp16(sa,      gp);
    cp16(sa + 16, gp + 16);
}

// EPI: 0=f32, 2=bf16 2-limb, 3=bf16 3-limb.  BIAS: 0 none, 1 per-col, 2 per-row.
template<int LIMBS, int EPI, int BIAS>
__global__ __launch_bounds__(256)
void mma_nt(GArgs ga)
{
    constexpr int NT_ = (LIMBS == 3) ? 6 : 3;
    constexpr u32 STAGE = (u32)(2 * LIMBS) * TILEB;

    extern __shared__ char dynsmem[];
    const u32 base = (s2u(dynsmem) + 127u) & ~127u;

    const int tid  = threadIdx.x;
    const int lane = tid & 31;
    const int wid  = tid >> 5;
    const int n0 = blockIdx.x * 128;
    const int m0 = blockIdx.y * 128;
    const int z  = blockIdx.z;

    const __nv_bfloat16* Ap[3];
    const __nv_bfloat16* Bp[3];
    Ap[0] = ga.A0 + (size_t)z * ga.sA;
    Ap[1] = ga.A1 + (size_t)z * ga.sA;
    Ap[2] = (LIMBS == 3) ? (ga.A2 + (size_t)z * ga.sA) : Ap[0];
    Bp[0] = ga.B0 + (size_t)z * ga.sB;
    Bp[1] = ga.B1 + (size_t)z * ga.sB;
    Bp[2] = (LIMBS == 3) ? (ga.B2 + (size_t)z * ga.sB) : Bp[0];

    // warp tile: 32(M) x 64(N)
    const int wm = (wid & 3) * 32;
    const int wn = (wid >> 2) * 64;

    float acc[2][8][4];
    #pragma unroll
    for (int i = 0; i < 2; i++)
        #pragma unroll
        for (int j = 0; j < 8; j++)
            #pragma unroll
            for (int k = 0; k < 4; k++) acc[i][j][k] = 0.f;

    // per-lane ldmatrix address bases (within a tile)
    const u32 lrow = (u32)(lane & 15) * ROWB + (u32)(lane >> 4) * 16;

    const int nch = ga.K >> 5;

    // prologue: chunk 0 -> stage 0
    {
        #pragma unroll
        for (int l = 0; l < LIMBS; l++) {
            cp_tile(Ap[l], m0, 0, ga.ldA, base + l * TILEB);
            cp_tile(Bp[l], n0, 0, ga.ldB, base + (LIMBS + l) * TILEB);
        }
        CP_COMMIT();
    }

    for (int c = 0; c < nch; c++) {
        if (c + 1 < nch) {
            const u32 sb = base + ((c + 1) & 1) * STAGE;
            #pragma unroll
            for (int l = 0; l < LIMBS; l++) {
                cp_tile(Ap[l], m0, (c + 1) << 5, ga.ldA, sb + l * TILEB);
                cp_tile(Bp[l], n0, (c + 1) << 5, ga.ldB, sb + (LIMBS + l) * TILEB);
            }
            CP_COMMIT();
            CP_WAIT1();
        } else {
            CP_WAIT0();
        }
        __syncthreads();

        const u32 sb = base + (c & 1) * STAGE;
        const int TA[6] = {0, 0, 1, 1, 0, 2};
        const int TB[6] = {0, 1, 0, 1, 2, 0};
        #pragma unroll
        for (int q = 0; q < NT_; q++) {
            const u32 ab = sb + TA[q] * TILEB + wm * ROWB + lrow;
            const u32 bb = sb + (LIMBS + TB[q]) * TILEB + wn * ROWB + lrow;
            #pragma unroll
            for (int ks = 0; ks < 2; ks++) {
                u32 bfr[8][2];
                #pragma unroll
                for (int ng = 0; ng < 4; ng++) {
                    u32 r[4];
                    ldsm4(r, bb + ng * (16 * ROWB) + ks * 32);
                    bfr[2 * ng][0]     = r[0];
                    bfr[2 * ng][1]     = r[2];
                    bfr[2 * ng + 1][0] = r[1];
                    bfr[2 * ng + 1][1] = r[3];
                }
                #pragma unroll
                for (int mt = 0; mt < 2; mt++) {
                    u32 afr[4];
                    ldsm4(afr, ab + mt * (16 * ROWB) + ks * 32);
                    #pragma unroll
                    for (int nt = 0; nt < 8; nt++)
                        mma16816(acc[mt][nt], afr, bfr[nt]);
                }
            }
        }
        __syncthreads();
    }

    // ---- epilogue ----
    #pragma unroll
    for (int mt = 0; mt < 2; mt++) {
        #pragma unroll
        for (int j = 0; j < 2; j++) {
            const size_t m = (size_t)m0 + wm + mt * 16 + (lane >> 2) + 8 * j;
            const size_t rowoff = (size_t)z * ga.sC + m * (size_t)ga.ldC;
            #pragma unroll
            for (int nt = 0; nt < 8; nt++) {
                const int col = n0 + wn + nt * 8 + (lane & 3) * 2;
                float v0 = acc[mt][nt][2 * j + 0];
                float v1 = acc[mt][nt][2 * j + 1];
                if (BIAS == 1) { v0 += ga.bias[col]; v1 += ga.bias[col + 1]; }
                if (BIAS == 2) { v0 += ga.bias[m];   v1 += ga.bias[m]; }
                const size_t off = rowoff + col;
                if (EPI == 0) {
                    *(float2*)(ga.Cf + off) = make_float2(v0, v1);
                } else if (EPI == 2) {
                    __nv_bfloat16 a0, a1, b0, b1;
                    split2(v0, a0, a1); split2(v1, b0, b1);
                    *(__nv_bfloat162*)(ga.C0 + off) = __nv_bfloat162(a0, b0);
                    *(__nv_bfloat162*)(ga.C1 + off) = __nv_bfloat162(a1, b1);
                } else {
                    __nv_bfloat16 a0, a1, a2, b0, b1, b2;
                    split3(v0, a0, a1, a2); split3(v1, b0, b1, b2);
                    *(__nv_bfloat162*)(ga.C0 + off) = __nv_bfloat162(a0, b0);
                    *(__nv_bfloat162*)(ga.C1 + off) = __nv_bfloat162(a1, b1);
                    *(__nv_bfloat162*)(ga.C2 + off) = __nv_bfloat162(a2, b2);
                }
            }
        }
    }
}

// ---------------- split kernels ----------------
__global__ void split3_k(const float* __restrict__ x,
                         __nv_bfloat16* o0, __nv_bfloat16* o1, __nv_bfloat16* o2)
{
    const int i = (blockIdx.x * blockDim.x + threadIdx.x) * 4;
    float4 v = *(const float4*)(x + i);
    float vv[4] = {v.x, v.y, v.z, v.w};
    __nv_bfloat16 h0[4], h1[4], h2[4];
    #pragma unroll
    for (int j = 0; j < 4; j++) split3(vv[j], h0[j], h1[j], h2[j]);
    *(__nv_bfloat162*)(o0 + i)     = __nv_bfloat162(h0[0], h0[1]);
    *(__nv_bfloat162*)(o0 + i + 2) = __nv_bfloat162(h0[2], h0[3]);
    *(__nv_bfloat162*)(o1 + i)     = __nv_bfloat162(h1[0], h1[1]);
    *(__nv_bfloat162*)(o1 + i + 2) = __nv_bfloat162(h1[2], h1[3]);
    *(__nv_bfloat162*)(o2 + i)     = __nv_bfloat162(h2[0], h2[1]);
    *(__nv_bfloat162*)(o2 + i + 2) = __nv_bfloat162(h2[2], h2[3]);
}
__global__ void split2_k(const float* __restrict__ x,
                         __nv_bfloat16* o0, __nv_bfloat16* o1)
{
    const int i = (blockIdx.x * blockDim.x + threadIdx.x) * 4;
    float4 v = *(const float4*)(x + i);
    float vv[4] = {v.x, v.y, v.z, v.w};
    __nv_bfloat16 h0[4], h1[4];
    #pragma unroll
    for (int j = 0; j < 4; j++) split2(vv[j], h0[j], h1[j]);
    *(__nv_bfloat162*)(o0 + i)     = __nv_bfloat162(h0[0], h0[1]);
    *(__nv_bfloat162*)(o0 + i + 2) = __nv_bfloat162(h0[2], h0[3]);
    *(__nv_bfloat162*)(o1 + i)     = __nv_bfloat162(h1[0], h1[1]);
    *(__nv_bfloat162*)(o1 + i + 2) = __nv_bfloat162(h1[2], h1[3]);
}
// transpose + 3-limb split of energy_W: Et[n][k] = eW[k][n]
__global__ void tsplit3_k(const float* __restrict__ w,
                          __nv_bfloat16* o0, __nv_bfloat16* o1, __nv_bfloat16* o2)
{
    __shared__ float t[32][33];
    const int bx = blockIdx.x * 32;
    const int by = blockIdx.y * 32;
    const int tx = threadIdx.x, ty = threadIdx.y;
    #pragma unroll
    for (int p = 0; p < 4; p++)
        t[ty + p * 8][tx] = w[(size_t)(by + ty + p * 8) * 1024 + bx + tx];
    __syncthreads();
    #pragma unroll
    for (int p = 0; p < 4; p++) {
        const int n = bx + ty + p * 8, k = by + tx;
        __nv_bfloat16 h0, h1, h2;
        split3(t[tx][ty + p * 8], h0, h1, h2);
        const size_t o = (size_t)n * 1024 + k;
        o0[o] = h0; o1[o] = h1; o2[o] = h2;
    }
}

// softmax of -energy with mask, in place, fused 2-limb split
__global__ void softmax_rows(float* __restrict__ attn, const int* __restrict__ mask,
                             __nv_bfloat16* __restrict__ L0, __nv_bfloat16* __restrict__ L1)
{
    __shared__ float red[256];
    const int row = blockIdx.x;
    const int q   = row & (S_DIM - 1);
    float* rp = attn + (size_t)row * S_DIM;
    const int* mp = mask + (size_t)q * S_DIM;
    const size_t lb = (size_t)row * S_DIM;
    const int t = threadIdx.x;

    float x[8];
    float mx = -3.402823e38f;
    #pragma unroll
    for (int r = 0; r < 8; r++) {
        const int j = t + r * 256;
        const float v = (mp[j] == 0) ? 1e9f : -rp[j];
        x[r] = v;
        mx = fmaxf(mx, v);
    }
    red[t] = mx; __syncthreads();
    #pragma unroll
    for (int s = 128; s > 0; s >>= 1) {
        if (t < s) red[t] = fmaxf(red[t], red[t + s]);
        __syncthreads();
    }
    mx = red[0]; __syncthreads();

    float ex[8], sum = 0.f;
    #pragma unroll
    for (int r = 0; r < 8; r++) { ex[r] = expf(x[r] - mx); sum += ex[r]; }
    red[t] = sum; __syncthreads();
    #pragma unroll
    for (int s = 128; s > 0; s >>= 1) {
        if (t < s) red[t] += red[t + s];
        __syncthreads();
    }
    const float inv = 1.0f / red[0];
    #pragma unroll
    for (int r = 0; r < 8; r++) {
        const int j = t + r * 256;
        const float p = ex[r] * inv;
        rp[j] = p;
        __nv_bfloat16 h0, h1;
        split2(p, h0, h1);
        L0[lb + j] = h0;
        L1[lb + j] = h1;
    }
}

// ---------------------------------------------------------------------------
extern "C" void kernel_launch(void* const* d_in, const int* in_sizes, int n_in,
                              void* d_out, int out_size)
{
    const float* query = (const float*)d_in[0];
    const float* key_  = (const float*)d_in[1];
    const float* value = (const float*)d_in[2];
    const int*   mask  = (const int*)  d_in[3];
    const float* Wq    = (const float*)d_in[4];
    const float* bq    = (const float*)d_in[5];
    const float* Wk    = (const float*)d_in[6];
    const float* bk    = (const float*)d_in[7];
    const float* Wv    = (const float*)d_in[8];
    const float* bv    = (const float*)d_in[9];
    const float* eW    = (const float*)d_in[10];

    float* outp = (float*)d_out;
    float* attn = outp + (size_t)B_DIM * S_DIM * E_DIM;

    __nv_bfloat16* S;
    cudaGetSymbolAddress((void**)&S, g_sb);

    __nv_bfloat16 *xq0 = S,          *xq1 = S + NQ,     *xq2 = S + 2*NQ;
    __nv_bfloat16 *xk0 = S + 3*NQ,   *xk1 = S + 4*NQ,   *xk2 = S + 5*NQ;
    __nv_bfloat16 *xv0 = S + 6*NQ,   *xv1 = S + 7*NQ;
    __nv_bfloat16 *Qp0 = S + 8*NQ,   *Qp1 = S + 9*NQ,   *Qp2 = S + 10*NQ;
    __nv_bfloat16 *Kp0 = S + 11*NQ,  *Kp1 = S + 12*NQ,  *Kp2 = S + 13*NQ;
    __nv_bfloat16 *KT0 = S + 14*NQ,  *KT1 = S + 15*NQ,  *KT2 = S + 16*NQ;
    __nv_bfloat16 *Vt0 = S + 17*NQ,  *Vt1 = S + 18*NQ;
    __nv_bfloat16 *at0 = S + 19*NQ,  *at1 = at0 + ATN;
    __nv_bfloat16 *W0  = S + 19*NQ + 2*ATN;
    __nv_bfloat16 *Wq0 = W0,         *Wq1 = W0 + WN,    *Wq2 = W0 + 2*WN;
    __nv_bfloat16 *Wk0 = W0 + 3*WN,  *Wk1 = W0 + 4*WN,  *Wk2 = W0 + 5*WN;
    __nv_bfloat16 *Wv0 = W0 + 6*WN,  *Wv1 = W0 + 7*WN;
    __nv_bfloat16 *Et0 = W0 + 8*WN,  *Et1 = W0 + 9*WN,  *Et2 = W0 + 10*WN;

    const int SM3 = 2 * 6 * TILEB + 256;   // 123 KB
    const int SM2 = 2 * 4 * TILEB + 256;   //  82 KB
    cudaFuncSetAttribute(mma_nt<3,3,1>, cudaFuncAttributeMaxDynamicSharedMemorySize, SM3);
    cudaFuncSetAttribute(mma_nt<3,3,0>, cudaFuncAttributeMaxDynamicSharedMemorySize, SM3);
    cudaFuncSetAttribute(mma_nt<3,0,0>, cudaFuncAttributeMaxDynamicSharedMemorySize, SM3);
    cudaFuncSetAttribute(mma_nt<2,2,2>, cudaFuncAttributeMaxDynamicSharedMemorySize, SM2);
    cudaFuncSetAttribute(mma_nt<2,0,0>, cudaFuncAttributeMaxDynamicSharedMemorySize, SM2);

    // input splits
    split3_k<<<NQ/1024, 256>>>(query, xq0, xq1, xq2);
    split3_k<<<NQ/1024, 256>>>(key_,  xk0, xk1, xk2);
    split2_k<<<NQ/1024, 256>>>(value, xv0, xv1);
    split3_k<<<WN/1024, 256>>>(Wq, Wq0, Wq1, Wq2);
    split3_k<<<WN/1024, 256>>>(Wk, Wk0, Wk1, Wk2);
    split2_k<<<WN/1024, 256>>>(Wv, Wv0, Wv1);
    tsplit3_k<<<dim3(32,32), dim3(32,8)>>>(eW, Et0, Et1, Et2);

    GArgs ga;
    ga.bias = nullptr; ga.Cf = nullptr; ga.C0 = ga.C1 = ga.C2 = nullptr;
    ga.sA = ga.sB = ga.sC = 0;

    // Q = query@Wq^T + bq -> 3-limb split
    ga.A0 = xq0; ga.A1 = xq1; ga.A2 = xq2;
    ga.B0 = Wq0; ga.B1 = Wq1; ga.B2 = Wq2;
    ga.bias = bq; ga.C0 = Qp0; ga.C1 = Qp1; ga.C2 = Qp2;
    ga.ldA = 1024; ga.ldB = 1024; ga.ldC = 1024; ga.K = 1024;
    mma_nt<3,3,1><<<dim3(8,128,1), 256, SM3>>>(ga);

    // K = key@Wk^T + bk
    ga.A0 = xk0; ga.A1 = xk1; ga.A2 = xk2;
    ga.B0 = Wk0; ga.B1 = Wk1; ga.B2 = Wk2;
    ga.bias = bk; ga.C0 = Kp0; ga.C1 = Kp1; ga.C2 = Kp2;
    mma_nt<3,3,1><<<dim3(8,128,1), 256, SM3>>>(ga);

    // Vt[e][token] = Wv@value^T + bv (per-row bias) -> 2-limb, ldC=16384
    ga.A0 = Wv0; ga.A1 = Wv1; ga.A2 = nullptr;
    ga.B0 = xv0; ga.B1 = xv1; ga.B2 = nullptr;
    ga.bias = bv; ga.C0 = Vt0; ga.C1 = Vt1; ga.C2 = nullptr;
    ga.ldA = 1024; ga.ldB = 1024; ga.ldC = 16384; ga.K = 1024;
    mma_nt<2,2,2><<<dim3(128,8,1), 256, SM2>>>(ga);

    // KT = K @ eW (NT against transposed eW) -> 3-limb
    ga.A0 = Kp0; ga.A1 = Kp1; ga.A2 = Kp2;
    ga.B0 = Et0; ga.B1 = Et1; ga.B2 = Et2;
    ga.bias = nullptr; ga.C0 = KT0; ga.C1 = KT1; ga.C2 = KT2;
    ga.ldA = 1024; ga.ldB = 1024; ga.ldC = 1024; ga.K = 1024;
    mma_nt<3,3,0><<<dim3(8,128,1), 256, SM3>>>(ga);

    // energy[b] = Q_b @ KT_b^T -> fp32 into attn region
    ga.A0 = Qp0; ga.A1 = Qp1; ga.A2 = Qp2;
    ga.B0 = KT0; ga.B1 = KT1; ga.B2 = KT2;
    ga.C0 = ga.C1 = ga.C2 = nullptr; ga.Cf = attn;
    ga.ldA = 1024; ga.ldB = 1024; ga.ldC = 2048; ga.K = 1024;
    ga.sA = (long long)S_DIM * 1024; ga.sB = (long long)S_DIM * 1024;
    ga.sC = (long long)S_DIM * S_DIM;
    mma_nt<3,0,0><<<dim3(16,16,8), 256, SM3>>>(ga);

    // softmax(-energy) in place + fused 2-limb split
    softmax_rows<<<MS, 256>>>(attn, mask, at0, at1);

    // out[b] = attn_b @ V_b (NT against Vt columns) -> fp32
    ga.A0 = at0; ga.A1 = at1; ga.A2 = nullptr;
    ga.B0 = Vt0; ga.B1 = Vt1; ga.B2 = nullptr;
    ga.Cf = outp;
    ga.ldA = 2048; ga.ldB = 16384; ga.ldC = 1024; ga.K = 2048;
    ga.sA = (long long)S_DIM * S_DIM; ga.sB = S_DIM;
    ga.sC = (long long)S_DIM * 1024;
    mma_nt<2,0,0><<<dim3(8,16,8), 256, SM2>>>(ga);
}

// round 6
// speedup vs baseline: 1.5222x; 1.0141x over previous
#include <cuda_runtime.h>
#include <cuda_bf16.h>
#include <cstdint>
#include <math.h>

// EBMAttention B=8,S=2048,E=1024 — all GEMMs via mma.sync bf16 (HMMA) with
// error-compensated limb splitting. PTX target is plain sm_100 (no tcgen05).
#define E_DIM 1024
#define S_DIM 2048
#define B_DIM 8
#define MS    16384

typedef unsigned int u32;
typedef unsigned long long u64;

#define NQ  16777216ull
#define WN  1048576ull
#define ATN 33554432ull
__device__ __align__(256) __nv_bfloat16 g_sb[19 * NQ + 2 * ATN + 11 * WN];

// ---------------- PTX helpers (all legal on sm_100 baseline) ----------------
__device__ __forceinline__ u32 s2u(const void* p) {
    return (u32)__cvta_generic_to_shared(p);
}
__device__ __forceinline__ void cp16(u32 sa, const void* gp) {
    asm volatile("cp.async.cg.shared.global [%0], [%1], 16;" :: "r"(sa), "l"(gp) : "memory");
}
#define CP_COMMIT() asm volatile("cp.async.commit_group;" ::: "memory")
template<int N>
__device__ __forceinline__ void cp_wait() {
    asm volatile("cp.async.wait_group %0;" :: "n"(N) : "memory");
}

__device__ __forceinline__ void ldsm4(u32* r, u32 addr) {
    asm volatile("ldmatrix.sync.aligned.m8n8.x4.shared.b16 {%0,%1,%2,%3}, [%4];"
                 : "=r"(r[0]), "=r"(r[1]), "=r"(r[2]), "=r"(r[3]) : "r"(addr));
}
__device__ __forceinline__ void mma16816(float* c, const u32* a, const u32* b) {
    asm volatile(
        "mma.sync.aligned.m16n8k16.row.col.f32.bf16.bf16.f32 "
        "{%0,%1,%2,%3}, {%4,%5,%6,%7}, {%8,%9}, {%0,%1,%2,%3};"
        : "+f"(c[0]), "+f"(c[1]), "+f"(c[2]), "+f"(c[3])
        : "r"(a[0]), "r"(a[1]), "r"(a[2]), "r"(a[3]), "r"(b[0]), "r"(b[1]));
}

__device__ __forceinline__ void split3(float x, __nv_bfloat16& h0, __nv_bfloat16& h1, __nv_bfloat16& h2) {
    h0 = __float2bfloat16(x);
    float r = x - __bfloat162float(h0);
    h1 = __float2bfloat16(r);
    h2 = __float2bfloat16(r - __bfloat162float(h1));
}
__device__ __forceinline__ void split2(float x, __nv_bfloat16& h0, __nv_bfloat16& h1) {
    h0 = __float2bfloat16(x);
    h1 = __float2bfloat16(x - __bfloat162float(h0));
}

struct GArgs {
    const __nv_bfloat16 *A0, *A1, *A2, *B0, *B1, *B2;
    const float* bias;
    float* Cf;
    __nv_bfloat16 *C0, *C1, *C2;
    int ldA, ldB, ldC, K;
    long long sA, sB, sC;
};

// CTA 128x128, BK=32 (64B rows), smem rows padded to 80B (bank-conflict-free
// ldmatrix: bank stride 20 -> 8 consecutive rows hit distinct bank groups).
#define ROWB  80
#define TILEB (128 * ROWB)   // 10240 B per 128x32 bf16 tile

__device__ __forceinline__ void cp_tile(const __nv_bfloat16* __restrict__ src,
                                        int row0, int k0, int ld, u32 sbase)
{
    const int t   = threadIdx.x;
    const int row = t >> 1;
    const int cb  = (t & 1) * 32;
    const char* gp = (const char*)(src + (size_t)(row0 + row) * ld + k0) + cb;
    const u32 sa = sbase + (u32)(row * ROWB + cb);
    cp16(sa,      gp);
    cp16(sa + 16, gp + 16);
}

// EPI: 0=f32, 2=bf16 2-limb, 3=bf16 3-limb.  BIAS: 0 none, 1 per-col, 2 per-row.
// NSTAGE: cp.async pipeline depth (2 for LIMBS=2 -> 2 CTA/SM; 3 for LIMBS=3).
template<int LIMBS, int EPI, int BIAS, int NSTAGE>
__global__ __launch_bounds__(256)
void mma_nt(GArgs ga)
{
    constexpr int NT_ = (LIMBS == 3) ? 6 : 3;
    constexpr u32 STAGE = (u32)(2 * LIMBS) * TILEB;

    extern __shared__ char dynsmem[];
    const u32 base = (s2u(dynsmem) + 127u) & ~127u;

    const int tid  = threadIdx.x;
    const int lane = tid & 31;
    const int wid  = tid >> 5;
    const int n0 = blockIdx.x * 128;
    const int m0 = blockIdx.y * 128;
    const int z  = blockIdx.z;

    const __nv_bfloat16* Ap[3];
    const __nv_bfloat16* Bp[3];
    Ap[0] = ga.A0 + (size_t)z * ga.sA;
    Ap[1] = ga.A1 + (size_t)z * ga.sA;
    Ap[2] = (LIMBS == 3) ? (ga.A2 + (size_t)z * ga.sA) : Ap[0];
    Bp[0] = ga.B0 + (size_t)z * ga.sB;
    Bp[1] = ga.B1 + (size_t)z * ga.sB;
    Bp[2] = (LIMBS == 3) ? (ga.B2 + (size_t)z * ga.sB) : Bp[0];

    // warp tile: 32(M) x 64(N)
    const int wm = (wid & 3) * 32;
    const int wn = (wid >> 2) * 64;

    float acc[2][8][4];
    #pragma unroll
    for (int i = 0; i < 2; i++)
        #pragma unroll
        for (int j = 0; j < 8; j++)
            #pragma unroll
            for (int k = 0; k < 4; k++) acc[i][j][k] = 0.f;

    const u32 lrow = (u32)(lane & 15) * ROWB + (u32)(lane >> 4) * 16;
    const int nch = ga.K >> 5;

    // prologue: chunks 0..NSTAGE-2
    #pragma unroll
    for (int pc = 0; pc < NSTAGE - 1; pc++) {
        const u32 sb = base + pc * STAGE;
        #pragma unroll
        for (int l = 0; l < LIMBS; l++) {
            cp_tile(Ap[l], m0, pc << 5, ga.ldA, sb + l * TILEB);
            cp_tile(Bp[l], n0, pc << 5, ga.ldB, sb + (LIMBS + l) * TILEB);
        }
        CP_COMMIT();
    }

    for (int c = 0; c < nch; c++) {
        cp_wait<NSTAGE - 2>();
        __syncthreads();   // chunk c visible to all; all done reading stage being refilled

        if (c + NSTAGE - 1 < nch) {
            const int pc = c + NSTAGE - 1;
            const u32 sb2 = base + (pc % NSTAGE) * STAGE;
            #pragma unroll
            for (int l = 0; l < LIMBS; l++) {
                cp_tile(Ap[l], m0, pc << 5, ga.ldA, sb2 + l * TILEB);
                cp_tile(Bp[l], n0, pc << 5, ga.ldB, sb2 + (LIMBS + l) * TILEB);
            }
            CP_COMMIT();
        }

        const u32 sb = base + (c % NSTAGE) * STAGE;
        #pragma unroll
        for (int ks = 0; ks < 2; ks++) {
            u32 afr[LIMBS][2][4];
            u32 bfr[LIMBS][8][2];
            #pragma unroll
            for (int l = 0; l < LIMBS; l++) {
                const u32 ab = sb + l * TILEB + wm * ROWB + lrow + ks * 32;
                #pragma unroll
                for (int mt = 0; mt < 2; mt++)
                    ldsm4(afr[l][mt], ab + mt * (16 * ROWB));
                const u32 bb = sb + (LIMBS + l) * TILEB + wn * ROWB + lrow + ks * 32;
                #pragma unroll
                for (int ng = 0; ng < 4; ng++) {
                    u32 r[4];
                    ldsm4(r, bb + ng * (16 * ROWB));
                    bfr[l][2 * ng][0]     = r[0];
                    bfr[l][2 * ng][1]     = r[2];
                    bfr[l][2 * ng + 1][0] = r[1];
                    bfr[l][2 * ng + 1][1] = r[3];
                }
            }
            const int TA[6] = {0, 0, 1, 1, 0, 2};
            const int TB[6] = {0, 1, 0, 1, 2, 0};
            #pragma unroll
            for (int q = 0; q < NT_; q++) {
                #pragma unroll
                for (int mt = 0; mt < 2; mt++)
                    #pragma unroll
                    for (int nt = 0; nt < 8; nt++)
                        mma16816(acc[mt][nt], afr[TA[q]][mt], bfr[TB[q]][nt]);
            }
        }
    }

    // ---- epilogue ----
    #pragma unroll
    for (int mt = 0; mt < 2; mt++) {
        #pragma unroll
        for (int j = 0; j < 2; j++) {
            const size_t m = (size_t)m0 + wm + mt * 16 + (lane >> 2) + 8 * j;
            const size_t rowoff = (size_t)z * ga.sC + m * (size_t)ga.ldC;
            #pragma unroll
            for (int nt = 0; nt < 8; nt++) {
                const int col = n0 + wn + nt * 8 + (lane & 3) * 2;
                float v0 = acc[mt][nt][2 * j + 0];
                float v1 = acc[mt][nt][2 * j + 1];
                if (BIAS == 1) { v0 += ga.bias[col]; v1 += ga.bias[col + 1]; }
                if (BIAS == 2) { v0 += ga.bias[m];   v1 += ga.bias[m]; }
                const size_t off = rowoff + col;
                if (EPI == 0) {
                    *(float2*)(ga.Cf + off) = make_float2(v0, v1);
                } else if (EPI == 2) {
                    __nv_bfloat16 a0, a1, b0, b1;
                    split2(v0, a0, a1); split2(v1, b0, b1);
                    *(__nv_bfloat162*)(ga.C0 + off) = __nv_bfloat162(a0, b0);
                    *(__nv_bfloat162*)(ga.C1 + off) = __nv_bfloat162(a1, b1);
                } else {
                    __nv_bfloat16 a0, a1, a2, b0, b1, b2;
                    split3(v0, a0, a1, a2); split3(v1, b0, b1, b2);
                    *(__nv_bfloat162*)(ga.C0 + off) = __nv_bfloat162(a0, b0);
                    *(__nv_bfloat162*)(ga.C1 + off) = __nv_bfloat162(a1, b1);
                    *(__nv_bfloat162*)(ga.C2 + off) = __nv_bfloat162(a2, b2);
                }
            }
        }
    }
}

// ---------------- split kernels ----------------
__global__ void split3_k(const float* __restrict__ x,
                         __nv_bfloat16* o0, __nv_bfloat16* o1, __nv_bfloat16* o2)
{
    const int i = (blockIdx.x * blockDim.x + threadIdx.x) * 4;
    float4 v = *(const float4*)(x + i);
    float vv[4] = {v.x, v.y, v.z, v.w};
    __nv_bfloat16 h0[4], h1[4], h2[4];
    #pragma unroll
    for (int j = 0; j < 4; j++) split3(vv[j], h0[j], h1[j], h2[j]);
    *(__nv_bfloat162*)(o0 + i)     = __nv_bfloat162(h0[0], h0[1]);
    *(__nv_bfloat162*)(o0 + i + 2) = __nv_bfloat162(h0[2], h0[3]);
    *(__nv_bfloat162*)(o1 + i)     = __nv_bfloat162(h1[0], h1[1]);
    *(__nv_bfloat162*)(o1 + i + 2) = __nv_bfloat162(h1[2], h1[3]);
    *(__nv_bfloat162*)(o2 + i)     = __nv_bfloat162(h2[0], h2[1]);
    *(__nv_bfloat162*)(o2 + i + 2) = __nv_bfloat162(h2[2], h2[3]);
}
__global__ void split2_k(const float* __restrict__ x,
                         __nv_bfloat16* o0, __nv_bfloat16* o1)
{
    const int i = (blockIdx.x * blockDim.x + threadIdx.x) * 4;
    float4 v = *(const float4*)(x + i);
    float vv[4] = {v.x, v.y, v.z, v.w};
    __nv_bfloat16 h0[4], h1[4];
    #pragma unroll
    for (int j = 0; j < 4; j++) split2(vv[j], h0[j], h1[j]);
    *(__nv_bfloat162*)(o0 + i)     = __nv_bfloat162(h0[0], h0[1]);
    *(__nv_bfloat162*)(o0 + i + 2) = __nv_bfloat162(h0[2], h0[3]);
    *(__nv_bfloat162*)(o1 + i)     = __nv_bfloat162(h1[0], h1[1]);
    *(__nv_bfloat162*)(o1 + i + 2) = __nv_bfloat162(h1[2], h1[3]);
}
// transpose + 3-limb split of energy_W: Et[n][k] = eW[k][n]
__global__ void tsplit3_k(const float* __restrict__ w,
                          __nv_bfloat16* o0, __nv_bfloat16* o1, __nv_bfloat16* o2)
{
    __shared__ float t[32][33];
    const int bx = blockIdx.x * 32;
    const int by = blockIdx.y * 32;
    const int tx = threadIdx.x, ty = threadIdx.y;
    #pragma unroll
    for (int p = 0; p < 4; p++)
        t[ty + p * 8][tx] = w[(size_t)(by + ty + p * 8) * 1024 + bx + tx];
    __syncthreads();
    #pragma unroll
    for (int p = 0; p < 4; p++) {
        const int n = bx + ty + p * 8, k = by + tx;
        __nv_bfloat16 h0, h1, h2;
        split3(t[tx][ty + p * 8], h0, h1, h2);
        const size_t o = (size_t)n * 1024 + k;
        o0[o] = h0; o1[o] = h1; o2[o] = h2;
    }
}

// softmax of -energy with mask, in place, fused 2-limb split
__global__ void softmax_rows(float* __restrict__ attn, const int* __restrict__ mask,
                             __nv_bfloat16* __restrict__ L0, __nv_bfloat16* __restrict__ L1)
{
    __shared__ float red[256];
    const int row = blockIdx.x;
    const int q   = row & (S_DIM - 1);
    float* rp = attn + (size_t)row * S_DIM;
    const int* mp = mask + (size_t)q * S_DIM;
    const size_t lb = (size_t)row * S_DIM;
    const int t = threadIdx.x;

    float x[8];
    float mx = -3.402823e38f;
    #pragma unroll
    for (int r = 0; r < 8; r++) {
        const int j = t + r * 256;
        const float v = (mp[j] == 0) ? 1e9f : -rp[j];
        x[r] = v;
        mx = fmaxf(mx, v);
    }
    red[t] = mx; __syncthreads();
    #pragma unroll
    for (int s = 128; s > 0; s >>= 1) {
        if (t < s) red[t] = fmaxf(red[t], red[t + s]);
        __syncthreads();
    }
    mx = red[0]; __syncthreads();

    float ex[8], sum = 0.f;
    #pragma unroll
    for (int r = 0; r < 8; r++) { ex[r] = expf(x[r] - mx); sum += ex[r]; }
    red[t] = sum; __syncthreads();
    #pragma unroll
    for (int s = 128; s > 0; s >>= 1) {
        if (t < s) red[t] += red[t + s];
        __syncthreads();
    }
    const float inv = 1.0f / red[0];
    #pragma unroll
    for (int r = 0; r < 8; r++) {
        const int j = t + r * 256;
        const float p = ex[r] * inv;
        rp[j] = p;
        __nv_bfloat16 h0, h1;
        split2(p, h0, h1);
        L0[lb + j] = h0;
        L1[lb + j] = h1;
    }
}

// ---------------------------------------------------------------------------
extern "C" void kernel_launch(void* const* d_in, const int* in_sizes, int n_in,
                              void* d_out, int out_size)
{
    const float* query = (const float*)d_in[0];
    const float* key_  = (const float*)d_in[1];
    const float* value = (const float*)d_in[2];
    const int*   mask  = (const int*)  d_in[3];
    const float* Wq    = (const float*)d_in[4];
    const float* bq    = (const float*)d_in[5];
    const float* Wk    = (const float*)d_in[6];
    const float* bk    = (const float*)d_in[7];
    const float* Wv    = (const float*)d_in[8];
    const float* bv    = (const float*)d_in[9];
    const float* eW    = (const float*)d_in[10];

    float* outp = (float*)d_out;
    float* attn = outp + (size_t)B_DIM * S_DIM * E_DIM;

    __nv_bfloat16* S;
    cudaGetSymbolAddress((void**)&S, g_sb);

    __nv_bfloat16 *xq0 = S,          *xq1 = S + NQ,     *xq2 = S + 2*NQ;
    __nv_bfloat16 *xk0 = S + 3*NQ,   *xk1 = S + 4*NQ,   *xk2 = S + 5*NQ;
    __nv_bfloat16 *xv0 = S + 6*NQ,   *xv1 = S + 7*NQ;
    __nv_bfloat16 *Qp0 = S + 8*NQ,   *Qp1 = S + 9*NQ,   *Qp2 = S + 10*NQ;
    __nv_bfloat16 *Kp0 = S + 11*NQ,  *Kp1 = S + 12*NQ,  *Kp2 = S + 13*NQ;
    __nv_bfloat16 *KT0 = S + 14*NQ,  *KT1 = S + 15*NQ,  *KT2 = S + 16*NQ;
    __nv_bfloat16 *Vt0 = S + 17*NQ,  *Vt1 = S + 18*NQ;
    __nv_bfloat16 *at0 = S + 19*NQ,  *at1 = at0 + ATN;
    __nv_bfloat16 *W0  = S + 19*NQ + 2*ATN;
    __nv_bfloat16 *Wq0 = W0,         *Wq1 = W0 + WN,    *Wq2 = W0 + 2*WN;
    __nv_bfloat16 *Wk0 = W0 + 3*WN,  *Wk1 = W0 + 4*WN,  *Wk2 = W0 + 5*WN;
    __nv_bfloat16 *Wv0 = W0 + 6*WN,  *Wv1 = W0 + 7*WN;
    __nv_bfloat16 *Et0 = W0 + 8*WN,  *Et1 = W0 + 9*WN,  *Et2 = W0 + 10*WN;

    const int SM3 = 3 * 6 * TILEB + 256;   // ~180 KB, 3-stage
    const int SM2 = 2 * 4 * TILEB + 256;   // ~80 KB, 2-stage -> 2 CTA/SM
    cudaFuncSetAttribute(mma_nt<3,3,1,3>, cudaFuncAttributeMaxDynamicSharedMemorySize, SM3);
    cudaFuncSetAttribute(mma_nt<3,3,0,3>, cudaFuncAttributeMaxDynamicSharedMemorySize, SM3);
    cudaFuncSetAttribute(mma_nt<3,0,0,3>, cudaFuncAttributeMaxDynamicSharedMemorySize, SM3);
    cudaFuncSetAttribute(mma_nt<2,2,2,2>, cudaFuncAttributeMaxDynamicSharedMemorySize, SM2);
    cudaFuncSetAttribute(mma_nt<2,0,0,2>, cudaFuncAttributeMaxDynamicSharedMemorySize, SM2);

    // input splits
    split3_k<<<NQ/1024, 256>>>(query, xq0, xq1, xq2);
    split3_k<<<NQ/1024, 256>>>(key_,  xk0, xk1, xk2);
    split2_k<<<NQ/1024, 256>>>(value, xv0, xv1);
    split3_k<<<WN/1024, 256>>>(Wq, Wq0, Wq1, Wq2);
    split3_k<<<WN/1024, 256>>>(Wk, Wk0, Wk1, Wk2);
    split2_k<<<WN/1024, 256>>>(Wv, Wv0, Wv1);
    tsplit3_k<<<dim3(32,32), dim3(32,8)>>>(eW, Et0, Et1, Et2);

    GArgs ga;
    ga.bias = nullptr; ga.Cf = nullptr; ga.C0 = ga.C1 = ga.C2 = nullptr;
    ga.sA = ga.sB = ga.sC = 0;

    // Q = query@Wq^T + bq -> 3-limb split
    ga.A0 = xq0; ga.A1 = xq1; ga.A2 = xq2;
    ga.B0 = Wq0; ga.B1 = Wq1; ga.B2 = Wq2;
    ga.bias = bq; ga.C0 = Qp0; ga.C1 = Qp1; ga.C2 = Qp2;
    ga.ldA = 1024; ga.ldB = 1024; ga.ldC = 1024; ga.K = 1024;
    mma_nt<3,3,1,3><<<dim3(8,128,1), 256, SM3>>>(ga);

    // K = key@Wk^T + bk
    ga.A0 = xk0; ga.A1 = xk1; ga.A2 = xk2;
    ga.B0 = Wk0; ga.B1 = Wk1; ga.B2 = Wk2;
    ga.bias = bk; ga.C0 = Kp0; ga.C1 = Kp1; ga.C2 = Kp2;
    mma_nt<3,3,1,3><<<dim3(8,128,1), 256, SM3>>>(ga);

    // Vt[e][token] = Wv@value^T + bv (per-row bias) -> 2-limb, ldC=16384
    ga.A0 = Wv0; ga.A1 = Wv1; ga.A2 = nullptr;
    ga.B0 = xv0; ga.B1 = xv1; ga.B2 = nullptr;
    ga.bias = bv; ga.C0 = Vt0; ga.C1 = Vt1; ga.C2 = nullptr;
    ga.ldA = 1024; ga.ldB = 1024; ga.ldC = 16384; ga.K = 1024;
    mma_nt<2,2,2,2><<<dim3(128,8,1), 256, SM2>>>(ga);

    // KT = K @ eW (NT against transposed eW) -> 3-limb
    ga.A0 = Kp0; ga.A1 = Kp1; ga.A2 = Kp2;
    ga.B0 = Et0; ga.B1 = Et1; ga.B2 = Et2;
    ga.bias = nullptr; ga.C0 = KT0; ga.C1 = KT1; ga.C2 = KT2;
    ga.ldA = 1024; ga.ldB = 1024; ga.ldC = 1024; ga.K = 1024;
    mma_nt<3,3,0,3><<<dim3(8,128,1), 256, SM3>>>(ga);

    // energy[b] = Q_b @ KT_b^T -> fp32 into attn region
    ga.A0 = Qp0; ga.A1 = Qp1; ga.A2 = Qp2;
    ga.B0 = KT0; ga.B1 = KT1; ga.B2 = KT2;
    ga.C0 = ga.C1 = ga.C2 = nullptr; ga.Cf = attn;
    ga.ldA = 1024; ga.ldB = 1024; ga.ldC = 2048; ga.K = 1024;
    ga.sA = (long long)S_DIM * 1024; ga.sB = (long long)S_DIM * 1024;
    ga.sC = (long long)S_DIM * S_DIM;
    mma_nt<3,0,0,3><<<dim3(16,16,8), 256, SM3>>>(ga);

    // softmax(-energy) in place + fused 2-limb split
    softmax_rows<<<MS, 256>>>(attn, mask, at0, at1);

    // out[b] = attn_b @ V_b (NT against Vt columns) -> fp32
    ga.A0 = at0; ga.A1 = at1; ga.A2 = nullptr;
    ga.B0 = Vt0; ga.B1 = Vt1; ga.B2 = nullptr;
    ga.Cf = outp;
    ga.ldA = 2048; ga.ldB = 16384; ga.ldC = 1024; ga.K = 2048;
    ga.sA = (long long)S_DIM * S_DIM; ga.sB = S_DIM;
    ga.sC = (long long)S_DIM * 1024;
    mma_nt<2,0,0,2><<<dim3(8,16,8), 256, SM2>>>(ga);
}